// round 9
// baseline (speedup 1.0000x reference)
#include <cuda_runtime.h>
#include <cuda_fp16.h>
#include <cstdint>

static constexpr int BATCH = 4;
static constexpr int SEQ   = 2048;
static constexpr int DIM   = 1024;

// Scratch (device globals: allocation-guard safe), all fp16 operands
__device__ __half g_x [BATCH * SEQ * DIM];
__device__ __half g_wq[DIM * DIM];
__device__ __half g_wk[DIM * DIM];
__device__ __half g_wv[DIM * DIM];
__device__ __half g_q [BATCH * SEQ * DIM];
__device__ __half g_k [BATCH * SEQ * DIM];
__device__ __half g_v [BATCH * SEQ * DIM];
__device__ __half g_vt[BATCH * DIM * SEQ];   // V^T: [B][D][S]
__device__ __half g_p [BATCH * SEQ * SEQ];   // fp16 attention weights

// ---------------------------------------------------------------------------
__device__ __forceinline__ void mma_f16(float (&c)[4],
                                        uint32_t a0, uint32_t a1,
                                        uint32_t a2, uint32_t a3,
                                        uint32_t b0, uint32_t b1) {
    asm volatile(
        "mma.sync.aligned.m16n8k16.row.col.f32.f16.f16.f32 "
        "{%0,%1,%2,%3}, {%4,%5,%6,%7}, {%8,%9}, {%0,%1,%2,%3};\n"
        : "+f"(c[0]), "+f"(c[1]), "+f"(c[2]), "+f"(c[3])
        : "r"(a0), "r"(a1), "r"(a2), "r"(a3), "r"(b0), "r"(b1));
}

#define CPA16(dst, src) \
    asm volatile("cp.async.cg.shared.global [%0], [%1], 16;\n" :: "r"(dst), "l"(src))

// ---------------------------------------------------------------------------
// fp32 -> fp16 conversion pass
// ---------------------------------------------------------------------------
__global__ __launch_bounds__(256)
void cvt_half_kernel(const float* __restrict__ in, __half* __restrict__ out, int n4)
{
    int i = blockIdx.x * 256 + threadIdx.x;
    if (i < n4) {
        float4 v = ((const float4*)in)[i];
        __half2 h01 = __floats2half2_rn(v.x, v.y);
        __half2 h23 = __floats2half2_rn(v.z, v.w);
        uint2 pk;
        pk.x = *(uint32_t*)&h01;
        pk.y = *(uint32_t*)&h23;
        ((uint2*)out)[i] = pk;
    }
}

// ---------------------------------------------------------------------------
// FP16 tensor-core GEMM (fp32 accum):  C = alpha * (A @ B^T) + bias
//   A [M,K], B [N,K], row-major fp16. Batched via blockIdx.z strides.
// 128x128 block tile, BK=32, 128 threads (4 warps, 64x64 warp tiles),
// 3-stage cp.async ring, mma.m16n8k16, 2 CTAs/SM.
//   HALF_OUT: store C as fp16 (operand reuse); else fp32.
// ---------------------------------------------------------------------------
template <bool HALF_OUT>
__global__ __launch_bounds__(128, 2)
void gemm_h(const __half* __restrict__ A, const __half* __restrict__ B,
            const float* __restrict__ bias, void* __restrict__ C,
            int M, int N, int K, float alpha, long sA, long sB, long sC)
{
    constexpr int BM = 128, BK = 32, NST = 3;
    constexpr int PH = 40;                     // row pitch in halves (80B)
    constexpr int TILE_H = BM * PH;            // halves per tile
    constexpr int STG_H  = 2 * TILE_H;         // A+B per stage

    extern __shared__ __half smh[];
    uint32_t sbase;
    asm("{ .reg .u64 t; cvta.to.shared.u64 t, %1; cvt.u32.u64 %0, t; }"
        : "=r"(sbase) : "l"(smh));

    const __half* Ab = A + (long)blockIdx.z * sA;
    const __half* Bb = B + (long)blockIdx.z * sB;

    const int n0   = blockIdx.x * 128;
    const int m0   = blockIdx.y * BM;
    const int tid  = threadIdx.x;
    const int warp = tid >> 5;
    const int lane = tid & 31;
    const int g    = lane >> 2;
    const int tg   = lane & 3;
    const int wm   = (warp & 1) * 64;
    const int wn   = (warp >> 1) * 64;

    float acc[4][8][4];
    #pragma unroll
    for (int i = 0; i < 4; ++i)
        #pragma unroll
        for (int j = 0; j < 8; ++j)
            #pragma unroll
            for (int r = 0; r < 4; ++r) acc[i][j][r] = 0.0f;

    // loader: 128 threads, each owns one row of A tile and one row of B tile
    auto load_tile = [&](int kt, int s) {
        const int k0 = kt * BK;
        const uint32_t a_off = sbase + (uint32_t)(s * STG_H) * 2u;
        const uint32_t b_off = a_off + (uint32_t)TILE_H * 2u;
        const __half* asrc = Ab + (long)(m0 + tid) * K + k0;
        const __half* bsrc = Bb + (long)(n0 + tid) * K + k0;
        const uint32_t arow = a_off + (uint32_t)(tid * PH) * 2u;
        const uint32_t brow = b_off + (uint32_t)(tid * PH) * 2u;
        #pragma unroll
        for (int c = 0; c < 4; ++c) CPA16(arow + c * 16, asrc + c * 8);
        #pragma unroll
        for (int c = 0; c < 4; ++c) CPA16(brow + c * 16, bsrc + c * 8);
        asm volatile("cp.async.commit_group;\n");
    };

    const int ntiles = K / BK;
    load_tile(0, 0);
    load_tile(1, 1);

    for (int kt = 0; kt < ntiles; ++kt) {
        const int s = kt % NST;
        if (kt + 2 < ntiles) load_tile(kt + 2, (kt + 2) % NST);
        else asm volatile("cp.async.commit_group;\n");
        asm volatile("cp.async.wait_group 2;\n");
        __syncthreads();

        const __half* As = smh + s * STG_H;
        const __half* Bs = As + TILE_H;

        #pragma unroll
        for (int kk = 0; kk < 2; ++kk) {       // 2 x K=16 per BK=32
            const int ko = kk * 16;
            uint32_t af[4][4];
            #pragma unroll
            for (int mi = 0; mi < 4; ++mi) {
                const __half* ap = &As[(wm + mi * 16 + g) * PH + ko + 2 * tg];
                af[mi][0] = *(const uint32_t*)ap;
                af[mi][1] = *(const uint32_t*)(ap + 8 * PH);
                af[mi][2] = *(const uint32_t*)(ap + 8);
                af[mi][3] = *(const uint32_t*)(ap + 8 * PH + 8);
            }
            uint32_t bf[8][2];
            #pragma unroll
            for (int ni = 0; ni < 8; ++ni) {
                const __half* bp = &Bs[(wn + ni * 8 + g) * PH + ko + 2 * tg];
                bf[ni][0] = *(const uint32_t*)bp;
                bf[ni][1] = *(const uint32_t*)(bp + 8);
            }
            #pragma unroll
            for (int mi = 0; mi < 4; ++mi)
                #pragma unroll
                for (int ni = 0; ni < 8; ++ni)
                    mma_f16(acc[mi][ni], af[mi][0], af[mi][1], af[mi][2],
                            af[mi][3], bf[ni][0], bf[ni][1]);
        }
        __syncthreads();
    }

    // Epilogue
    #pragma unroll
    for (int mi = 0; mi < 4; ++mi) {
        const int row = m0 + wm + mi * 16 + g;
        #pragma unroll
        for (int ni = 0; ni < 8; ++ni) {
            const int col = n0 + wn + ni * 8 + tg * 2;
            float v0 = acc[mi][ni][0] * alpha, v1 = acc[mi][ni][1] * alpha;
            float v2 = acc[mi][ni][2] * alpha, v3 = acc[mi][ni][3] * alpha;
            if (bias) {
                float2 b = *(const float2*)&bias[col];
                v0 += b.x; v1 += b.y; v2 += b.x; v3 += b.y;
            }
            if (HALF_OUT) {
                __half* Cb = (__half*)C + (long)blockIdx.z * sC;
                __half2 h0 = __floats2half2_rn(v0, v1);
                __half2 h1 = __floats2half2_rn(v2, v3);
                *(__half2*)&Cb[(long)row * N + col]       = h0;
                *(__half2*)&Cb[(long)(row + 8) * N + col] = h1;
            } else {
                float* Cb = (float*)C + (long)blockIdx.z * sC;
                *(float2*)&Cb[(long)row * N + col]       = make_float2(v0, v1);
                *(float2*)&Cb[(long)(row + 8) * N + col] = make_float2(v2, v3);
            }
        }
    }
}

// ---------------------------------------------------------------------------
// V transpose (fp16): [B][S][D] -> [B][D][S]
// ---------------------------------------------------------------------------
__global__ __launch_bounds__(256)
void transpose_h(const __half* __restrict__ in, __half* __restrict__ out)
{
    __shared__ __half t[32][34];
    const __half* ib = in  + (long)blockIdx.z * SEQ * DIM;
    __half*       ob = out + (long)blockIdx.z * DIM * SEQ;
    const int d0 = blockIdx.x * 32;
    const int s0 = blockIdx.y * 32;
    const int tx = threadIdx.x;
    const int ty = threadIdx.y;
    #pragma unroll
    for (int j = 0; j < 32; j += 8)
        t[ty + j][tx] = ib[(long)(s0 + ty + j) * DIM + d0 + tx];
    __syncthreads();
    #pragma unroll
    for (int j = 0; j < 32; j += 8)
        ob[(long)(d0 + ty + j) * SEQ + s0 + tx] = t[tx][ty + j];
}

// ---------------------------------------------------------------------------
// In-place row softmax (exact fp32) + fp16 copy for the AV GEMM
// ---------------------------------------------------------------------------
__global__ __launch_bounds__(256)
void softmax_kernel(float* __restrict__ data, __half* __restrict__ ph)
{
    constexpr int NC = SEQ;
    constexpr int PT = NC / 256;

    const long roff = (long)blockIdx.x * NC;
    float*  row = data + roff;
    __half* rh  = ph + roff;
    __shared__ float red[8];

    const int tid  = threadIdx.x;
    const int lane = tid & 31;
    const int warp = tid >> 5;

    float v[PT];
    #pragma unroll
    for (int i = 0; i < PT; ++i) v[i] = row[tid + i * 256];

    float lmax = v[0];
    #pragma unroll
    for (int i = 1; i < PT; ++i) lmax = fmaxf(lmax, v[i]);
    #pragma unroll
    for (int o = 16; o > 0; o >>= 1)
        lmax = fmaxf(lmax, __shfl_xor_sync(0xFFFFFFFFu, lmax, o));
    if (lane == 0) red[warp] = lmax;
    __syncthreads();
    float rmax = red[0];
    #pragma unroll
    for (int w = 1; w < 8; ++w) rmax = fmaxf(rmax, red[w]);
    __syncthreads();

    float lsum = 0.0f;
    #pragma unroll
    for (int i = 0; i < PT; ++i) {
        v[i] = __expf(v[i] - rmax);
        lsum += v[i];
    }
    #pragma unroll
    for (int o = 16; o > 0; o >>= 1)
        lsum += __shfl_xor_sync(0xFFFFFFFFu, lsum, o);
    if (lane == 0) red[warp] = lsum;
    __syncthreads();
    float rsum = 0.0f;
    #pragma unroll
    for (int w = 0; w < 8; ++w) rsum += red[w];

    const float inv = 1.0f / rsum;
    #pragma unroll
    for (int i = 0; i < PT; ++i) {
        const int idx = tid + i * 256;
        const float o = v[i] * inv;
        row[idx] = o;
        rh[idx]  = __float2half_rn(o);
    }
}

// ---------------------------------------------------------------------------
// Launch: cvt(x,W) -> QKV proj -> V^T -> scores -> softmax -> AV
// Output layout: [weighted_sum B*S*D | attention_weights B*S*S]
// ---------------------------------------------------------------------------
extern "C" void kernel_launch(void* const* d_in, const int* in_sizes, int n_in,
                              void* d_out, int out_size)
{
    const float* x  = (const float*)d_in[0];
    const float* Wq = (const float*)d_in[1];
    const float* bq = (const float*)d_in[2];
    const float* Wk = (const float*)d_in[3];
    const float* bk = (const float*)d_in[4];
    const float* Wv = (const float*)d_in[5];
    const float* bv = (const float*)d_in[6];

    float* out_ws = (float*)d_out;
    float* out_aw = (float*)d_out + (long)BATCH * SEQ * DIM;

    __half *xh, *wq, *wk, *wv, *q, *k, *v, *vt, *p;
    cudaGetSymbolAddress((void**)&xh, g_x);
    cudaGetSymbolAddress((void**)&wq, g_wq);
    cudaGetSymbolAddress((void**)&wk, g_wk);
    cudaGetSymbolAddress((void**)&wv, g_wv);
    cudaGetSymbolAddress((void**)&q,  g_q);
    cudaGetSymbolAddress((void**)&k,  g_k);
    cudaGetSymbolAddress((void**)&v,  g_v);
    cudaGetSymbolAddress((void**)&vt, g_vt);
    cudaGetSymbolAddress((void**)&p,  g_p);

    // smem: 3 stages x 2 tiles x 128 rows x 40 halves x 2B = 61440 B
    const int smem_sz = 3 * 2 * 128 * 40 * 2;
    cudaFuncSetAttribute(gemm_h<true >, cudaFuncAttributeMaxDynamicSharedMemorySize, smem_sz);
    cudaFuncSetAttribute(gemm_h<false>, cudaFuncAttributeMaxDynamicSharedMemorySize, smem_sz);

    const dim3 blk(128);
    const dim3 blk256(256);

    // 0) convert inputs to fp16
    {
        const int nx = BATCH * SEQ * DIM / 4;
        const int nw = DIM * DIM / 4;
        cvt_half_kernel<<<(nx + 255) / 256, blk256>>>(x,  xh, nx);
        cvt_half_kernel<<<(nw + 255) / 256, blk256>>>(Wq, wq, nw);
        cvt_half_kernel<<<(nw + 255) / 256, blk256>>>(Wk, wk, nw);
        cvt_half_kernel<<<(nw + 255) / 256, blk256>>>(Wv, wv, nw);
    }

    // 1) QKV projections: [8192,1024] = xh @ W^T + b, fp16 outputs
    {
        dim3 grid(DIM / 128, (BATCH * SEQ) / 128, 1);
        gemm_h<true><<<grid, blk, smem_sz>>>(xh, wq, bq, q,
                                             BATCH * SEQ, DIM, DIM, 1.0f, 0, 0, 0);
        gemm_h<true><<<grid, blk, smem_sz>>>(xh, wk, bk, k,
                                             BATCH * SEQ, DIM, DIM, 1.0f, 0, 0, 0);
        gemm_h<true><<<grid, blk, smem_sz>>>(xh, wv, bv, v,
                                             BATCH * SEQ, DIM, DIM, 1.0f, 0, 0, 0);
    }

    // 2) V^T: [S,D] -> [D,S] fp16
    {
        dim3 tgrid(DIM / 32, SEQ / 32, BATCH);
        transpose_h<<<tgrid, dim3(32, 8)>>>(v, vt);
    }

    // 3) scores = (Q @ K^T) / 32, fp32 store into attention-weights region
    {
        dim3 grid(SEQ / 128, SEQ / 128, BATCH);
        gemm_h<false><<<grid, blk, smem_sz>>>(q, k, nullptr, out_aw,
                                              SEQ, SEQ, DIM, 0.03125f,
                                              (long)SEQ * DIM, (long)SEQ * DIM,
                                              (long)SEQ * SEQ);
    }

    // 4) softmax: exact fp32 -> out_aw, fp16 -> p
    softmax_kernel<<<BATCH * SEQ, blk256>>>(out_aw, p);

    // 5) weighted_sum = P @ Vt^T  (Vt: [D,S] = B[N=D,K=S]), fp32 out
    {
        dim3 grid(DIM / 128, SEQ / 128, BATCH);
        gemm_h<false><<<grid, blk, smem_sz>>>(p, vt, nullptr, out_ws,
                                              SEQ, DIM, SEQ, 1.0f,
                                              (long)SEQ * SEQ, (long)DIM * SEQ,
                                              (long)SEQ * DIM);
    }
}

// round 10
// speedup vs baseline: 1.1530x; 1.1530x over previous
#include <cuda_runtime.h>
#include <cuda_fp16.h>
#include <cstdint>

static constexpr int BATCH = 4;
static constexpr int SEQ   = 2048;
static constexpr int DIM   = 1024;

// Scratch (device globals: allocation-guard safe), all fp16 operands
__device__ __half g_x [BATCH * SEQ * DIM];
__device__ __half g_wq[DIM * DIM];
__device__ __half g_wk[DIM * DIM];
__device__ __half g_wv[DIM * DIM];
__device__ __half g_q [BATCH * SEQ * DIM];
__device__ __half g_k [BATCH * SEQ * DIM];
__device__ __half g_v [BATCH * SEQ * DIM];
__device__ __half g_vt[BATCH * DIM * SEQ];   // V^T: [B][D][S]
__device__ __half g_p [BATCH * SEQ * SEQ];   // fp16 attention weights

// ---------------------------------------------------------------------------
__device__ __forceinline__ void mma_f16(float (&c)[4],
                                        uint32_t a0, uint32_t a1,
                                        uint32_t a2, uint32_t a3,
                                        uint32_t b0, uint32_t b1) {
    asm volatile(
        "mma.sync.aligned.m16n8k16.row.col.f32.f16.f16.f32 "
        "{%0,%1,%2,%3}, {%4,%5,%6,%7}, {%8,%9}, {%0,%1,%2,%3};\n"
        : "+f"(c[0]), "+f"(c[1]), "+f"(c[2]), "+f"(c[3])
        : "r"(a0), "r"(a1), "r"(a2), "r"(a3), "r"(b0), "r"(b1));
}

#define CPA16(dst, src) \
    asm volatile("cp.async.cg.shared.global [%0], [%1], 16;\n" :: "r"(dst), "l"(src))

// ---------------------------------------------------------------------------
// fp32 -> fp16 conversion pass
// ---------------------------------------------------------------------------
__global__ __launch_bounds__(256)
void cvt_half_kernel(const float* __restrict__ in, __half* __restrict__ out, int n4)
{
    int i = blockIdx.x * 256 + threadIdx.x;
    if (i < n4) {
        float4 v = ((const float4*)in)[i];
        __half2 h01 = __floats2half2_rn(v.x, v.y);
        __half2 h23 = __floats2half2_rn(v.z, v.w);
        uint2 pk;
        pk.x = *(uint32_t*)&h01;
        pk.y = *(uint32_t*)&h23;
        ((uint2*)out)[i] = pk;
    }
}

// ---------------------------------------------------------------------------
// FP16 tensor-core GEMM (fp32 accum):  C = alpha * (A @ B^T) + bias
//   A [M,K], B [N,K], row-major fp16. Batched via blockIdx.z strides.
// 128x128 block tile, BK=64, 256 threads (8 warps, 64x32 warp tiles),
// 3-stage cp.async ring, mma.m16n8k16, 2 CTAs/SM.
//   HALF_OUT: store C as fp16 (operand reuse); else fp32.
// ---------------------------------------------------------------------------
template <bool HALF_OUT>
__global__ __launch_bounds__(256, 2)
void gemm_h(const __half* __restrict__ A, const __half* __restrict__ B,
            const float* __restrict__ bias, void* __restrict__ C,
            int M, int N, int K, float alpha, long sA, long sB, long sC)
{
    constexpr int BM = 128, BK = 64, NST = 3;
    constexpr int PH = 72;                     // row pitch in halves (144B)
    constexpr int TILE_H = BM * PH;            // halves per tile
    constexpr int STG_H  = 2 * TILE_H;         // A+B per stage

    extern __shared__ __half smh[];
    uint32_t sbase;
    asm("{ .reg .u64 t; cvta.to.shared.u64 t, %1; cvt.u32.u64 %0, t; }"
        : "=r"(sbase) : "l"(smh));

    const __half* Ab = A + (long)blockIdx.z * sA;
    const __half* Bb = B + (long)blockIdx.z * sB;

    const int n0   = blockIdx.x * 128;
    const int m0   = blockIdx.y * BM;
    const int tid  = threadIdx.x;
    const int warp = tid >> 5;
    const int lane = tid & 31;
    const int g    = lane >> 2;
    const int tg   = lane & 3;
    const int wm   = (warp & 1) * 64;
    const int wn   = (warp >> 1) * 32;

    // loader indices: 128 rows, 2 threads/row, each thread 4 x 16B chunks
    const int cr = tid >> 1;                  // 0..127 row
    const int ck = (tid & 1) * 32;            // k offset (halves): 0 or 32

    float acc[4][4][4];
    #pragma unroll
    for (int i = 0; i < 4; ++i)
        #pragma unroll
        for (int j = 0; j < 4; ++j)
            #pragma unroll
            for (int r = 0; r < 4; ++r) acc[i][j][r] = 0.0f;

    auto load_tile = [&](int kt, int s) {
        const int k0 = kt * BK;
        const uint32_t a_dst = sbase + (uint32_t)(s * STG_H + cr * PH + ck) * 2u;
        const uint32_t b_dst = a_dst + (uint32_t)TILE_H * 2u;
        const __half* asrc = Ab + (long)(m0 + cr) * K + k0 + ck;
        const __half* bsrc = Bb + (long)(n0 + cr) * K + k0 + ck;
        #pragma unroll
        for (int c = 0; c < 4; ++c) CPA16(a_dst + c * 16, asrc + c * 8);
        #pragma unroll
        for (int c = 0; c < 4; ++c) CPA16(b_dst + c * 16, bsrc + c * 8);
        asm volatile("cp.async.commit_group;\n");
    };

    const int ntiles = K / BK;
    load_tile(0, 0);
    load_tile(1, 1);

    for (int kt = 0; kt < ntiles; ++kt) {
        const int s = kt % NST;
        if (kt + 2 < ntiles) load_tile(kt + 2, (kt + 2) % NST);
        else asm volatile("cp.async.commit_group;\n");
        asm volatile("cp.async.wait_group 2;\n");
        __syncthreads();

        const __half* As = smh + s * STG_H;
        const __half* Bs = As + TILE_H;

        #pragma unroll
        for (int kk = 0; kk < 4; ++kk) {       // 4 x K=16 per BK=64
            const int ko = kk * 16;
            uint32_t af[4][4];
            #pragma unroll
            for (int mi = 0; mi < 4; ++mi) {
                const __half* ap = &As[(wm + mi * 16 + g) * PH + ko + 2 * tg];
                af[mi][0] = *(const uint32_t*)ap;
                af[mi][1] = *(const uint32_t*)(ap + 8 * PH);
                af[mi][2] = *(const uint32_t*)(ap + 8);
                af[mi][3] = *(const uint32_t*)(ap + 8 * PH + 8);
            }
            uint32_t bf[4][2];
            #pragma unroll
            for (int ni = 0; ni < 4; ++ni) {
                const __half* bp = &Bs[(wn + ni * 8 + g) * PH + ko + 2 * tg];
                bf[ni][0] = *(const uint32_t*)bp;
                bf[ni][1] = *(const uint32_t*)(bp + 8);
            }
            #pragma unroll
            for (int mi = 0; mi < 4; ++mi)
                #pragma unroll
                for (int ni = 0; ni < 4; ++ni)
                    mma_f16(acc[mi][ni], af[mi][0], af[mi][1], af[mi][2],
                            af[mi][3], bf[ni][0], bf[ni][1]);
        }
        __syncthreads();
    }

    // Epilogue
    #pragma unroll
    for (int mi = 0; mi < 4; ++mi) {
        const int row = m0 + wm + mi * 16 + g;
        #pragma unroll
        for (int ni = 0; ni < 4; ++ni) {
            const int col = n0 + wn + ni * 8 + tg * 2;
            float v0 = acc[mi][ni][0] * alpha, v1 = acc[mi][ni][1] * alpha;
            float v2 = acc[mi][ni][2] * alpha, v3 = acc[mi][ni][3] * alpha;
            if (bias) {
                float2 b = *(const float2*)&bias[col];
                v0 += b.x; v1 += b.y; v2 += b.x; v3 += b.y;
            }
            if (HALF_OUT) {
                __half* Cb = (__half*)C + (long)blockIdx.z * sC;
                __half2 h0 = __floats2half2_rn(v0, v1);
                __half2 h1 = __floats2half2_rn(v2, v3);
                *(__half2*)&Cb[(long)row * N + col]       = h0;
                *(__half2*)&Cb[(long)(row + 8) * N + col] = h1;
            } else {
                float* Cb = (float*)C + (long)blockIdx.z * sC;
                *(float2*)&Cb[(long)row * N + col]       = make_float2(v0, v1);
                *(float2*)&Cb[(long)(row + 8) * N + col] = make_float2(v2, v3);
            }
        }
    }
}

// ---------------------------------------------------------------------------
// V transpose (fp16): [B][S][D] -> [B][D][S]
// ---------------------------------------------------------------------------
__global__ __launch_bounds__(256)
void transpose_h(const __half* __restrict__ in, __half* __restrict__ out)
{
    __shared__ __half t[32][34];
    const __half* ib = in  + (long)blockIdx.z * SEQ * DIM;
    __half*       ob = out + (long)blockIdx.z * DIM * SEQ;
    const int d0 = blockIdx.x * 32;
    const int s0 = blockIdx.y * 32;
    const int tx = threadIdx.x;
    const int ty = threadIdx.y;
    #pragma unroll
    for (int j = 0; j < 32; j += 8)
        t[ty + j][tx] = ib[(long)(s0 + ty + j) * DIM + d0 + tx];
    __syncthreads();
    #pragma unroll
    for (int j = 0; j < 32; j += 8)
        ob[(long)(d0 + ty + j) * SEQ + s0 + tx] = t[tx][ty + j];
}

// ---------------------------------------------------------------------------
// In-place row softmax (exact fp32) + fp16 copy for the AV GEMM
// ---------------------------------------------------------------------------
__global__ __launch_bounds__(256)
void softmax_kernel(float* __restrict__ data, __half* __restrict__ ph)
{
    constexpr int NC = SEQ;
    constexpr int PT = NC / 256;

    const long roff = (long)blockIdx.x * NC;
    float*  row = data + roff;
    __half* rh  = ph + roff;
    __shared__ float red[8];

    const int tid  = threadIdx.x;
    const int lane = tid & 31;
    const int warp = tid >> 5;

    float v[PT];
    #pragma unroll
    for (int i = 0; i < PT; ++i) v[i] = row[tid + i * 256];

    float lmax = v[0];
    #pragma unroll
    for (int i = 1; i < PT; ++i) lmax = fmaxf(lmax, v[i]);
    #pragma unroll
    for (int o = 16; o > 0; o >>= 1)
        lmax = fmaxf(lmax, __shfl_xor_sync(0xFFFFFFFFu, lmax, o));
    if (lane == 0) red[warp] = lmax;
    __syncthreads();
    float rmax = red[0];
    #pragma unroll
    for (int w = 1; w < 8; ++w) rmax = fmaxf(rmax, red[w]);
    __syncthreads();

    float lsum = 0.0f;
    #pragma unroll
    for (int i = 0; i < PT; ++i) {
        v[i] = __expf(v[i] - rmax);
        lsum += v[i];
    }
    #pragma unroll
    for (int o = 16; o > 0; o >>= 1)
        lsum += __shfl_xor_sync(0xFFFFFFFFu, lsum, o);
    if (lane == 0) red[warp] = lsum;
    __syncthreads();
    float rsum = 0.0f;
    #pragma unroll
    for (int w = 0; w < 8; ++w) rsum += red[w];

    const float inv = 1.0f / rsum;
    #pragma unroll
    for (int i = 0; i < PT; ++i) {
        const int idx = tid + i * 256;
        const float o = v[i] * inv;
        row[idx] = o;
        rh[idx]  = __float2half_rn(o);
    }
}

// ---------------------------------------------------------------------------
// Launch: cvt(x,W) -> QKV proj -> V^T -> scores -> softmax -> AV
// Output layout: [weighted_sum B*S*D | attention_weights B*S*S]
// ---------------------------------------------------------------------------
extern "C" void kernel_launch(void* const* d_in, const int* in_sizes, int n_in,
                              void* d_out, int out_size)
{
    const float* x  = (const float*)d_in[0];
    const float* Wq = (const float*)d_in[1];
    const float* bq = (const float*)d_in[2];
    const float* Wk = (const float*)d_in[3];
    const float* bk = (const float*)d_in[4];
    const float* Wv = (const float*)d_in[5];
    const float* bv = (const float*)d_in[6];

    float* out_ws = (float*)d_out;
    float* out_aw = (float*)d_out + (long)BATCH * SEQ * DIM;

    __half *xh, *wq, *wk, *wv, *q, *k, *v, *vt, *p;
    cudaGetSymbolAddress((void**)&xh, g_x);
    cudaGetSymbolAddress((void**)&wq, g_wq);
    cudaGetSymbolAddress((void**)&wk, g_wk);
    cudaGetSymbolAddress((void**)&wv, g_wv);
    cudaGetSymbolAddress((void**)&q,  g_q);
    cudaGetSymbolAddress((void**)&k,  g_k);
    cudaGetSymbolAddress((void**)&v,  g_v);
    cudaGetSymbolAddress((void**)&vt, g_vt);
    cudaGetSymbolAddress((void**)&p,  g_p);

    // smem: 3 stages x 2 tiles x 128 rows x 72 halves x 2B = 110592 B
    const int smem_sz = 3 * 2 * 128 * 72 * 2;
    cudaFuncSetAttribute(gemm_h<true >, cudaFuncAttributeMaxDynamicSharedMemorySize, smem_sz);
    cudaFuncSetAttribute(gemm_h<false>, cudaFuncAttributeMaxDynamicSharedMemorySize, smem_sz);

    const dim3 blk(256);

    // 0) convert inputs to fp16
    {
        const int nx = BATCH * SEQ * DIM / 4;
        const int nw = DIM * DIM / 4;
        cvt_half_kernel<<<(nx + 255) / 256, blk>>>(x,  xh, nx);
        cvt_half_kernel<<<(nw + 255) / 256, blk>>>(Wq, wq, nw);
        cvt_half_kernel<<<(nw + 255) / 256, blk>>>(Wk, wk, nw);
        cvt_half_kernel<<<(nw + 255) / 256, blk>>>(Wv, wv, nw);
    }

    // 1) QKV projections: [8192,1024] = xh @ W^T + b, fp16 outputs
    {
        dim3 grid(DIM / 128, (BATCH * SEQ) / 128, 1);
        gemm_h<true><<<grid, blk, smem_sz>>>(xh, wq, bq, q,
                                             BATCH * SEQ, DIM, DIM, 1.0f, 0, 0, 0);
        gemm_h<true><<<grid, blk, smem_sz>>>(xh, wk, bk, k,
                                             BATCH * SEQ, DIM, DIM, 1.0f, 0, 0, 0);
        gemm_h<true><<<grid, blk, smem_sz>>>(xh, wv, bv, v,
                                             BATCH * SEQ, DIM, DIM, 1.0f, 0, 0, 0);
    }

    // 2) V^T: [S,D] -> [D,S] fp16
    {
        dim3 tgrid(DIM / 32, SEQ / 32, BATCH);
        transpose_h<<<tgrid, dim3(32, 8)>>>(v, vt);
    }

    // 3) scores = (Q @ K^T) / 32, fp32 store into attention-weights region
    {
        dim3 grid(SEQ / 128, SEQ / 128, BATCH);
        gemm_h<false><<<grid, blk, smem_sz>>>(q, k, nullptr, out_aw,
                                              SEQ, SEQ, DIM, 0.03125f,
                                              (long)SEQ * DIM, (long)SEQ * DIM,
                                              (long)SEQ * SEQ);
    }

    // 4) softmax: exact fp32 -> out_aw, fp16 -> p
    softmax_kernel<<<BATCH * SEQ, blk>>>(out_aw, p);

    // 5) weighted_sum = P @ Vt^T  (Vt: [D,S] = B[N=D,K=S]), fp32 out
    {
        dim3 grid(DIM / 128, SEQ / 128, BATCH);
        gemm_h<false><<<grid, blk, smem_sz>>>(p, vt, nullptr, out_ws,
                                              SEQ, DIM, SEQ, 1.0f,
                                              (long)SEQ * SEQ, (long)DIM * SEQ,
                                              (long)SEQ * DIM);
    }
}

// round 11
// speedup vs baseline: 1.2997x; 1.1272x over previous
#include <cuda_runtime.h>
#include <cuda_fp16.h>
#include <cstdint>

static constexpr int BATCH = 4;
static constexpr int SEQ   = 2048;
static constexpr int DIM   = 1024;

// Scratch (device globals: allocation-guard safe), all fp16 operands
__device__ __half g_x [BATCH * SEQ * DIM];
__device__ __half g_wq[DIM * DIM];
__device__ __half g_wk[DIM * DIM];
__device__ __half g_wv[DIM * DIM];
__device__ __half g_q [BATCH * SEQ * DIM];
__device__ __half g_k [BATCH * SEQ * DIM];
__device__ __half g_v [BATCH * SEQ * DIM];
__device__ __half g_vt[BATCH * DIM * SEQ];   // V^T: [B][D][S]
__device__ __half g_p [BATCH * SEQ * SEQ];   // fp16 attention weights

// ---------------------------------------------------------------------------
__device__ __forceinline__ void mma_f16(float (&c)[4],
                                        uint32_t a0, uint32_t a1,
                                        uint32_t a2, uint32_t a3,
                                        uint32_t b0, uint32_t b1) {
    asm volatile(
        "mma.sync.aligned.m16n8k16.row.col.f32.f16.f16.f32 "
        "{%0,%1,%2,%3}, {%4,%5,%6,%7}, {%8,%9}, {%0,%1,%2,%3};\n"
        : "+f"(c[0]), "+f"(c[1]), "+f"(c[2]), "+f"(c[3])
        : "r"(a0), "r"(a1), "r"(a2), "r"(a3), "r"(b0), "r"(b1));
}

__device__ __forceinline__ void ldsm4(uint32_t& r0, uint32_t& r1,
                                      uint32_t& r2, uint32_t& r3, uint32_t addr) {
    asm volatile(
        "ldmatrix.sync.aligned.m8n8.x4.shared.b16 {%0,%1,%2,%3}, [%4];"
        : "=r"(r0), "=r"(r1), "=r"(r2), "=r"(r3) : "r"(addr));
}

#define CPA16(dst, src) \
    asm volatile("cp.async.cg.shared.global [%0], [%1], 16;\n" :: "r"(dst), "l"(src))

// ---------------------------------------------------------------------------
// fp32 -> fp16 conversion pass
// ---------------------------------------------------------------------------
__global__ __launch_bounds__(256)
void cvt_half_kernel(const float* __restrict__ in, __half* __restrict__ out, int n4)
{
    int i = blockIdx.x * 256 + threadIdx.x;
    if (i < n4) {
        float4 v = ((const float4*)in)[i];
        __half2 h01 = __floats2half2_rn(v.x, v.y);
        __half2 h23 = __floats2half2_rn(v.z, v.w);
        uint2 pk;
        pk.x = *(uint32_t*)&h01;
        pk.y = *(uint32_t*)&h23;
        ((uint2*)out)[i] = pk;
    }
}

// ---------------------------------------------------------------------------
// FP16 tensor-core GEMM (fp32 accum):  C = alpha * (A @ B^T) + bias
//   A [M,K], B [N,K], row-major fp16. Batched via blockIdx.z strides.
// 128x128 block tile, BK=32, 256 threads (8 warps, 64x32 warp tiles),
// double-buffered cp.async, ldmatrix fragment loads from XOR-swizzled
// 64B-row tiles, mma.m16n8k16, 2 CTAs/SM.
//   HALF_OUT: store C as fp16 (operand reuse); else fp32.
// ---------------------------------------------------------------------------
template <bool HALF_OUT>
__global__ __launch_bounds__(256, 2)
void gemm_h(const __half* __restrict__ A, const __half* __restrict__ B,
            const float* __restrict__ bias, void* __restrict__ C,
            int M, int N, int K, float alpha, long sA, long sB, long sC)
{
    constexpr int BK = 32;
    constexpr int TILE_H = 128 * 32;           // halves per tile (8 KB)
    constexpr int STG_H  = 2 * TILE_H;         // A+B per stage

    extern __shared__ __half smh[];
    uint32_t sbase;
    asm("{ .reg .u64 t; cvta.to.shared.u64 t, %1; cvt.u32.u64 %0, t; }"
        : "=r"(sbase) : "l"(smh));

    const __half* Ab = A + (long)blockIdx.z * sA;
    const __half* Bb = B + (long)blockIdx.z * sB;

    const int n0   = blockIdx.x * 128;
    const int m0   = blockIdx.y * 128;
    const int tid  = threadIdx.x;
    const int warp = tid >> 5;
    const int lane = tid & 31;
    const int g    = lane >> 2;
    const int tg   = lane & 3;
    const int wm   = (warp & 1) * 64;
    const int wn   = (warp >> 1) * 32;

    // Per-lane LDSM addressing (row within a 16-row group + chunk-high bit)
    const int lrow = ((lane >> 3) & 1) * 8 + (lane & 7);   // 0..15
    const uint32_t hi = lane >> 4;                          // 0/1

    uint32_t offA[4], swA[4];
    #pragma unroll
    for (int mi = 0; mi < 4; ++mi) {
        int r = wm + mi * 16 + lrow;
        offA[mi] = (uint32_t)r * 64u;
        swA[mi]  = ((uint32_t)r >> 1) & 3u;
    }
    uint32_t offB[2], swB[2];
    #pragma unroll
    for (int nj = 0; nj < 2; ++nj) {
        int r = wn + nj * 16 + lrow;
        offB[nj] = (uint32_t)r * 64u;
        swB[nj]  = ((uint32_t)r >> 1) & 3u;
    }

    float acc[4][4][4];
    #pragma unroll
    for (int i = 0; i < 4; ++i)
        #pragma unroll
        for (int j = 0; j < 4; ++j)
            #pragma unroll
            for (int r = 0; r < 4; ++r) acc[i][j][r] = 0.0f;

    // Loader: thread t -> row t>>1, 16B chunks 2(t&1), 2(t&1)+1 of A and B.
    // Swizzled store: chunk c at position c ^ ((row>>1)&3).
    auto load_tile = [&](int kt, int buf) {
        const int k0 = kt * BK;
        const int cr = tid >> 1;
        const int cp = (tid & 1) * 2;
        const uint32_t sw = ((uint32_t)cr >> 1) & 3u;
        const uint32_t abase = sbase + (uint32_t)(buf * STG_H) * 2u + (uint32_t)cr * 64u;
        const uint32_t bbase = abase + (uint32_t)TILE_H * 2u;
        const __half* asrc = Ab + (long)(m0 + cr) * K + k0 + cp * 8;
        const __half* bsrc = Bb + (long)(n0 + cr) * K + k0 + cp * 8;
        CPA16(abase + ((((uint32_t)cp    ) ^ sw) << 4), asrc);
        CPA16(abase + ((((uint32_t)cp + 1) ^ sw) << 4), asrc + 8);
        CPA16(bbase + ((((uint32_t)cp    ) ^ sw) << 4), bsrc);
        CPA16(bbase + ((((uint32_t)cp + 1) ^ sw) << 4), bsrc + 8);
        asm volatile("cp.async.commit_group;\n");
    };

    const int ntiles = K / BK;
    load_tile(0, 0);

    for (int kt = 0; kt < ntiles; ++kt) {
        const int buf = kt & 1;
        if (kt + 1 < ntiles) {
            load_tile(kt + 1, buf ^ 1);
            asm volatile("cp.async.wait_group 1;\n");
        } else {
            asm volatile("cp.async.wait_group 0;\n");
        }
        __syncthreads();

        const uint32_t Ab32 = sbase + (uint32_t)(buf * STG_H) * 2u;
        const uint32_t Bb32 = Ab32 + (uint32_t)TILE_H * 2u;

        #pragma unroll
        for (int kk = 0; kk < 2; ++kk) {       // 2 x K=16 per BK=32
            const uint32_t c0 = (uint32_t)(kk * 2) + hi;
            uint32_t af[4][4], bf[2][4];
            #pragma unroll
            for (int mi = 0; mi < 4; ++mi)
                ldsm4(af[mi][0], af[mi][1], af[mi][2], af[mi][3],
                      Ab32 + offA[mi] + ((c0 ^ swA[mi]) << 4));
            #pragma unroll
            for (int nj = 0; nj < 2; ++nj)
                ldsm4(bf[nj][0], bf[nj][1], bf[nj][2], bf[nj][3],
                      Bb32 + offB[nj] + ((c0 ^ swB[nj]) << 4));
            #pragma unroll
            for (int mi = 0; mi < 4; ++mi)
                #pragma unroll
                for (int ni = 0; ni < 4; ++ni) {
                    const int nj = ni >> 1, lo = ni & 1;
                    mma_f16(acc[mi][ni], af[mi][0], af[mi][1], af[mi][2],
                            af[mi][3], bf[nj][lo], bf[nj][2 + lo]);
                }
        }
        __syncthreads();
    }

    // Epilogue
    #pragma unroll
    for (int mi = 0; mi < 4; ++mi) {
        const int row = m0 + wm + mi * 16 + g;
        #pragma unroll
        for (int ni = 0; ni < 4; ++ni) {
            const int col = n0 + wn + ni * 8 + tg * 2;
            float v0 = acc[mi][ni][0] * alpha, v1 = acc[mi][ni][1] * alpha;
            float v2 = acc[mi][ni][2] * alpha, v3 = acc[mi][ni][3] * alpha;
            if (bias) {
                float2 b = *(const float2*)&bias[col];
                v0 += b.x; v1 += b.y; v2 += b.x; v3 += b.y;
            }
            if (HALF_OUT) {
                __half* Cb = (__half*)C + (long)blockIdx.z * sC;
                __half2 h0 = __floats2half2_rn(v0, v1);
                __half2 h1 = __floats2half2_rn(v2, v3);
                *(__half2*)&Cb[(long)row * N + col]       = h0;
                *(__half2*)&Cb[(long)(row + 8) * N + col] = h1;
            } else {
                float* Cb = (float*)C + (long)blockIdx.z * sC;
                *(float2*)&Cb[(long)row * N + col]       = make_float2(v0, v1);
                *(float2*)&Cb[(long)(row + 8) * N + col] = make_float2(v2, v3);
            }
        }
    }
}

// ---------------------------------------------------------------------------
// V transpose (fp16): [B][S][D] -> [B][D][S]
// ---------------------------------------------------------------------------
__global__ __launch_bounds__(256)
void transpose_h(const __half* __restrict__ in, __half* __restrict__ out)
{
    __shared__ __half t[32][34];
    const __half* ib = in  + (long)blockIdx.z * SEQ * DIM;
    __half*       ob = out + (long)blockIdx.z * DIM * SEQ;
    const int d0 = blockIdx.x * 32;
    const int s0 = blockIdx.y * 32;
    const int tx = threadIdx.x;
    const int ty = threadIdx.y;
    #pragma unroll
    for (int j = 0; j < 32; j += 8)
        t[ty + j][tx] = ib[(long)(s0 + ty + j) * DIM + d0 + tx];
    __syncthreads();
    #pragma unroll
    for (int j = 0; j < 32; j += 8)
        ob[(long)(d0 + ty + j) * SEQ + s0 + tx] = t[tx][ty + j];
}

// ---------------------------------------------------------------------------
// In-place row softmax (exact fp32) + fp16 copy for the AV GEMM
// ---------------------------------------------------------------------------
__global__ __launch_bounds__(256)
void softmax_kernel(float* __restrict__ data, __half* __restrict__ ph)
{
    constexpr int NC = SEQ;
    constexpr int PT = NC / 256;

    const long roff = (long)blockIdx.x * NC;
    float*  row = data + roff;
    __half* rh  = ph + roff;
    __shared__ float red[8];

    const int tid  = threadIdx.x;
    const int lane = tid & 31;
    const int warp = tid >> 5;

    float v[PT];
    #pragma unroll
    for (int i = 0; i < PT; ++i) v[i] = row[tid + i * 256];

    float lmax = v[0];
    #pragma unroll
    for (int i = 1; i < PT; ++i) lmax = fmaxf(lmax, v[i]);
    #pragma unroll
    for (int o = 16; o > 0; o >>= 1)
        lmax = fmaxf(lmax, __shfl_xor_sync(0xFFFFFFFFu, lmax, o));
    if (lane == 0) red[warp] = lmax;
    __syncthreads();
    float rmax = red[0];
    #pragma unroll
    for (int w = 1; w < 8; ++w) rmax = fmaxf(rmax, red[w]);
    __syncthreads();

    float lsum = 0.0f;
    #pragma unroll
    for (int i = 0; i < PT; ++i) {
        v[i] = __expf(v[i] - rmax);
        lsum += v[i];
    }
    #pragma unroll
    for (int o = 16; o > 0; o >>= 1)
        lsum += __shfl_xor_sync(0xFFFFFFFFu, lsum, o);
    if (lane == 0) red[warp] = lsum;
    __syncthreads();
    float rsum = 0.0f;
    #pragma unroll
    for (int w = 0; w < 8; ++w) rsum += red[w];

    const float inv = 1.0f / rsum;
    #pragma unroll
    for (int i = 0; i < PT; ++i) {
        const int idx = tid + i * 256;
        const float o = v[i] * inv;
        row[idx] = o;
        rh[idx]  = __float2half_rn(o);
    }
}

// ---------------------------------------------------------------------------
// Launch: cvt(x,W) -> QKV proj -> V^T -> scores -> softmax -> AV
// Output layout: [weighted_sum B*S*D | attention_weights B*S*S]
// ---------------------------------------------------------------------------
extern "C" void kernel_launch(void* const* d_in, const int* in_sizes, int n_in,
                              void* d_out, int out_size)
{
    const float* x  = (const float*)d_in[0];
    const float* Wq = (const float*)d_in[1];
    const float* bq = (const float*)d_in[2];
    const float* Wk = (const float*)d_in[3];
    const float* bk = (const float*)d_in[4];
    const float* Wv = (const float*)d_in[5];
    const float* bv = (const float*)d_in[6];

    float* out_ws = (float*)d_out;
    float* out_aw = (float*)d_out + (long)BATCH * SEQ * DIM;

    __half *xh, *wq, *wk, *wv, *q, *k, *v, *vt, *p;
    cudaGetSymbolAddress((void**)&xh, g_x);
    cudaGetSymbolAddress((void**)&wq, g_wq);
    cudaGetSymbolAddress((void**)&wk, g_wk);
    cudaGetSymbolAddress((void**)&wv, g_wv);
    cudaGetSymbolAddress((void**)&q,  g_q);
    cudaGetSymbolAddress((void**)&k,  g_k);
    cudaGetSymbolAddress((void**)&v,  g_v);
    cudaGetSymbolAddress((void**)&vt, g_vt);
    cudaGetSymbolAddress((void**)&p,  g_p);

    // smem: 2 stages x 2 tiles x 8192 B = 32768 B
    const int smem_sz = 2 * 2 * 128 * 32 * 2;
    cudaFuncSetAttribute(gemm_h<true >, cudaFuncAttributeMaxDynamicSharedMemorySize, smem_sz);
    cudaFuncSetAttribute(gemm_h<false>, cudaFuncAttributeMaxDynamicSharedMemorySize, smem_sz);

    const dim3 blk(256);

    // 0) convert inputs to fp16
    {
        const int nx = BATCH * SEQ * DIM / 4;
        const int nw = DIM * DIM / 4;
        cvt_half_kernel<<<(nx + 255) / 256, blk>>>(x,  xh, nx);
        cvt_half_kernel<<<(nw + 255) / 256, blk>>>(Wq, wq, nw);
        cvt_half_kernel<<<(nw + 255) / 256, blk>>>(Wk, wk, nw);
        cvt_half_kernel<<<(nw + 255) / 256, blk>>>(Wv, wv, nw);
    }

    // 1) QKV projections: [8192,1024] = xh @ W^T + b, fp16 outputs
    {
        dim3 grid(DIM / 128, (BATCH * SEQ) / 128, 1);
        gemm_h<true><<<grid, blk, smem_sz>>>(xh, wq, bq, q,
                                             BATCH * SEQ, DIM, DIM, 1.0f, 0, 0, 0);
        gemm_h<true><<<grid, blk, smem_sz>>>(xh, wk, bk, k,
                                             BATCH * SEQ, DIM, DIM, 1.0f, 0, 0, 0);
        gemm_h<true><<<grid, blk, smem_sz>>>(xh, wv, bv, v,
                                             BATCH * SEQ, DIM, DIM, 1.0f, 0, 0, 0);
    }

    // 2) V^T: [S,D] -> [D,S] fp16
    {
        dim3 tgrid(DIM / 32, SEQ / 32, BATCH);
        transpose_h<<<tgrid, dim3(32, 8)>>>(v, vt);
    }

    // 3) scores = (Q @ K^T) / 32, fp32 store into attention-weights region
    {
        dim3 grid(SEQ / 128, SEQ / 128, BATCH);
        gemm_h<false><<<grid, blk, smem_sz>>>(q, k, nullptr, out_aw,
                                              SEQ, SEQ, DIM, 0.03125f,
                                              (long)SEQ * DIM, (long)SEQ * DIM,
                                              (long)SEQ * SEQ);
    }

    // 4) softmax: exact fp32 -> out_aw, fp16 -> p
    softmax_kernel<<<BATCH * SEQ, blk>>>(out_aw, p);

    // 5) weighted_sum = P @ Vt^T  (Vt: [D,S] = B[N=D,K=S]), fp32 out
    {
        dim3 grid(DIM / 128, SEQ / 128, BATCH);
        gemm_h<false><<<grid, blk, smem_sz>>>(p, vt, nullptr, out_ws,
                                              SEQ, DIM, SEQ, 1.0f,
                                              (long)SEQ * SEQ, (long)DIM * SEQ,
                                              (long)SEQ * DIM);
    }
}

// round 12
// speedup vs baseline: 1.4035x; 1.0799x over previous
#include <cuda_runtime.h>
#include <cuda_fp16.h>
#include <cstdint>

static constexpr int BATCH = 4;
static constexpr int SEQ   = 2048;
static constexpr int DIM   = 1024;

// Scratch (device globals: allocation-guard safe)
__device__ __half g_x  [BATCH * SEQ * DIM];        // fp16 x
__device__ __half g_w  [3 * DIM * DIM];            // concat Wq|Wk|Wv fp16
__device__ float  g_b  [3 * DIM];                  // concat bq|bk|bv fp32
__device__ __half g_qkv[BATCH * SEQ * 3 * DIM];    // fused Q|K|V rows
__device__ __half g_vt [BATCH * DIM * SEQ];        // V^T: [B][D][S]
__device__ __half g_p  [BATCH * SEQ * SEQ];        // fp16 attention weights

// ---------------------------------------------------------------------------
__device__ __forceinline__ void mma_f16(float (&c)[4],
                                        uint32_t a0, uint32_t a1,
                                        uint32_t a2, uint32_t a3,
                                        uint32_t b0, uint32_t b1) {
    asm volatile(
        "mma.sync.aligned.m16n8k16.row.col.f32.f16.f16.f32 "
        "{%0,%1,%2,%3}, {%4,%5,%6,%7}, {%8,%9}, {%0,%1,%2,%3};\n"
        : "+f"(c[0]), "+f"(c[1]), "+f"(c[2]), "+f"(c[3])
        : "r"(a0), "r"(a1), "r"(a2), "r"(a3), "r"(b0), "r"(b1));
}

__device__ __forceinline__ void ldsm4(uint32_t& r0, uint32_t& r1,
                                      uint32_t& r2, uint32_t& r3, uint32_t addr) {
    asm volatile(
        "ldmatrix.sync.aligned.m8n8.x4.shared.b16 {%0,%1,%2,%3}, [%4];"
        : "=r"(r0), "=r"(r1), "=r"(r2), "=r"(r3) : "r"(addr));
}

#define CPA16(dst, src) \
    asm volatile("cp.async.cg.shared.global [%0], [%1], 16;\n" :: "r"(dst), "l"(src))

// ---------------------------------------------------------------------------
// fp32 -> fp16 conversion passes
// ---------------------------------------------------------------------------
__global__ __launch_bounds__(256)
void cvt_half_kernel(const float* __restrict__ in, __half* __restrict__ out, int n4)
{
    int i = blockIdx.x * 256 + threadIdx.x;
    if (i < n4) {
        float4 v = ((const float4*)in)[i];
        __half2 h01 = __floats2half2_rn(v.x, v.y);
        __half2 h23 = __floats2half2_rn(v.z, v.w);
        uint2 pk;
        pk.x = *(uint32_t*)&h01;
        pk.y = *(uint32_t*)&h23;
        ((uint2*)out)[i] = pk;
    }
}

// Converts 3 weight matrices into one concatenated fp16 buffer
__global__ __launch_bounds__(256)
void cvt3_kernel(const float* __restrict__ w0, const float* __restrict__ w1,
                 const float* __restrict__ w2, __half* __restrict__ out, int nw4)
{
    int i = blockIdx.x * 256 + threadIdx.x;
    if (i < 3 * nw4) {
        const float* src = (i < nw4) ? w0 : (i < 2 * nw4 ? w1 : w2);
        int j = (i < nw4) ? i : (i < 2 * nw4 ? i - nw4 : i - 2 * nw4);
        float4 v = ((const float4*)src)[j];
        __half2 h01 = __floats2half2_rn(v.x, v.y);
        __half2 h23 = __floats2half2_rn(v.z, v.w);
        uint2 pk;
        pk.x = *(uint32_t*)&h01;
        pk.y = *(uint32_t*)&h23;
        ((uint2*)out)[i] = pk;
    }
}

// Concatenate 3 bias vectors (DIM each)
__global__ __launch_bounds__(256)
void bias3_kernel(const float* __restrict__ b0, const float* __restrict__ b1,
                  const float* __restrict__ b2, float* __restrict__ out)
{
    int i = blockIdx.x * 256 + threadIdx.x;
    if (i < DIM)           out[i] = b0[i];
    else if (i < 2 * DIM)  out[i] = b1[i - DIM];
    else if (i < 3 * DIM)  out[i] = b2[i - 2 * DIM];
}

// ---------------------------------------------------------------------------
// FP16 tensor-core GEMM (fp32 accum):  C = alpha * (A @ B^T) + bias
//   A [M x K] lda, B [N x K] ldb, row-major fp16, explicit leading dims.
// 128x128 block tile, BK=32, 256 threads (8 warps, 64x32 warp tiles),
// 3-stage cp.async ring with ONE __syncthreads per K-tile, ldmatrix
// fragment loads from XOR-swizzled 64B-row tiles, mma.m16n8k16, 2 CTAs/SM.
//   HALF_OUT: store C fp16 (operand reuse); else fp32.
// ---------------------------------------------------------------------------
template <bool HALF_OUT>
__global__ __launch_bounds__(256, 2)
void gemm_h(const __half* __restrict__ A, const __half* __restrict__ B,
            const float* __restrict__ bias, void* __restrict__ C,
            int N, int K, int lda, int ldb, int ldc, float alpha,
            long sA, long sB, long sC)
{
    constexpr int BK = 32;
    constexpr int TILE_H = 128 * 32;           // halves per tile (8 KB)
    constexpr int STG_H  = 2 * TILE_H;         // A+B per stage

    extern __shared__ __half smh[];
    uint32_t sbase;
    asm("{ .reg .u64 t; cvta.to.shared.u64 t, %1; cvt.u32.u64 %0, t; }"
        : "=r"(sbase) : "l"(smh));

    const __half* Ab = A + (long)blockIdx.z * sA;
    const __half* Bb = B + (long)blockIdx.z * sB;

    const int n0   = blockIdx.x * 128;
    const int m0   = blockIdx.y * 128;
    const int tid  = threadIdx.x;
    const int warp = tid >> 5;
    const int lane = tid & 31;
    const int g    = lane >> 2;
    const int tg   = lane & 3;
    const int wm   = (warp & 1) * 64;
    const int wn   = (warp >> 1) * 32;

    // Per-lane LDSM addressing
    const int lrow = ((lane >> 3) & 1) * 8 + (lane & 7);   // 0..15
    const uint32_t hi = lane >> 4;                          // 0/1

    uint32_t offA[4], swA[4];
    #pragma unroll
    for (int mi = 0; mi < 4; ++mi) {
        int r = wm + mi * 16 + lrow;
        offA[mi] = (uint32_t)r * 64u;
        swA[mi]  = ((uint32_t)r >> 1) & 3u;
    }
    uint32_t offB[2], swB[2];
    #pragma unroll
    for (int nj = 0; nj < 2; ++nj) {
        int r = wn + nj * 16 + lrow;
        offB[nj] = (uint32_t)r * 64u;
        swB[nj]  = ((uint32_t)r >> 1) & 3u;
    }

    float acc[4][4][4];
    #pragma unroll
    for (int i = 0; i < 4; ++i)
        #pragma unroll
        for (int j = 0; j < 4; ++j)
            #pragma unroll
            for (int r = 0; r < 4; ++r) acc[i][j][r] = 0.0f;

    // Loader: thread t -> row t>>1, 16B chunks 2(t&1), 2(t&1)+1 of A and B.
    auto load_tile = [&](int kt, int s) {
        const int k0 = kt * BK;
        const int cr = tid >> 1;
        const int cp = (tid & 1) * 2;
        const uint32_t sw = ((uint32_t)cr >> 1) & 3u;
        const uint32_t abase = sbase + (uint32_t)(s * STG_H) * 2u + (uint32_t)cr * 64u;
        const uint32_t bbase = abase + (uint32_t)TILE_H * 2u;
        const __half* asrc = Ab + (long)(m0 + cr) * lda + k0 + cp * 8;
        const __half* bsrc = Bb + (long)(n0 + cr) * ldb + k0 + cp * 8;
        CPA16(abase + ((((uint32_t)cp    ) ^ sw) << 4), asrc);
        CPA16(abase + ((((uint32_t)cp + 1) ^ sw) << 4), asrc + 8);
        CPA16(bbase + ((((uint32_t)cp    ) ^ sw) << 4), bsrc);
        CPA16(bbase + ((((uint32_t)cp + 1) ^ sw) << 4), bsrc + 8);
        asm volatile("cp.async.commit_group;\n");
    };

    const int ntiles = K / BK;
    load_tile(0, 0);
    load_tile(1, 1);

    for (int kt = 0; kt < ntiles; ++kt) {
        const int s = kt % 3;
        if (kt + 1 < ntiles) asm volatile("cp.async.wait_group 1;\n");
        else                 asm volatile("cp.async.wait_group 0;\n");
        __syncthreads();
        // Safe: stage (kt+2)%3 was last read in iteration kt-1, and the
        // barrier above guarantees every warp finished that compute.
        if (kt + 2 < ntiles) load_tile(kt + 2, (kt + 2) % 3);

        const uint32_t Ab32 = sbase + (uint32_t)(s * STG_H) * 2u;
        const uint32_t Bb32 = Ab32 + (uint32_t)TILE_H * 2u;

        #pragma unroll
        for (int kk = 0; kk < 2; ++kk) {       // 2 x K=16 per BK=32
            const uint32_t c0 = (uint32_t)(kk * 2) + hi;
            uint32_t af[4][4], bf[2][4];
            #pragma unroll
            for (int mi = 0; mi < 4; ++mi)
                ldsm4(af[mi][0], af[mi][1], af[mi][2], af[mi][3],
                      Ab32 + offA[mi] + ((c0 ^ swA[mi]) << 4));
            #pragma unroll
            for (int nj = 0; nj < 2; ++nj)
                ldsm4(bf[nj][0], bf[nj][1], bf[nj][2], bf[nj][3],
                      Bb32 + offB[nj] + ((c0 ^ swB[nj]) << 4));
            #pragma unroll
            for (int mi = 0; mi < 4; ++mi)
                #pragma unroll
                for (int ni = 0; ni < 4; ++ni) {
                    const int nj = ni >> 1, lo = ni & 1;
                    mma_f16(acc[mi][ni], af[mi][0], af[mi][1], af[mi][2],
                            af[mi][3], bf[nj][lo], bf[nj][2 + lo]);
                }
        }
    }

    // Epilogue
    #pragma unroll
    for (int mi = 0; mi < 4; ++mi) {
        const int row = m0 + wm + mi * 16 + g;
        #pragma unroll
        for (int ni = 0; ni < 4; ++ni) {
            const int col = n0 + wn + ni * 8 + tg * 2;
            float v0 = acc[mi][ni][0] * alpha, v1 = acc[mi][ni][1] * alpha;
            float v2 = acc[mi][ni][2] * alpha, v3 = acc[mi][ni][3] * alpha;
            if (bias) {
                float2 b = *(const float2*)&bias[col];
                v0 += b.x; v1 += b.y; v2 += b.x; v3 += b.y;
            }
            if (HALF_OUT) {
                __half* Cb = (__half*)C + (long)blockIdx.z * sC;
                __half2 h0 = __floats2half2_rn(v0, v1);
                __half2 h1 = __floats2half2_rn(v2, v3);
                *(__half2*)&Cb[(long)row * ldc + col]       = h0;
                *(__half2*)&Cb[(long)(row + 8) * ldc + col] = h1;
            } else {
                float* Cb = (float*)C + (long)blockIdx.z * sC;
                *(float2*)&Cb[(long)row * ldc + col]       = make_float2(v0, v1);
                *(float2*)&Cb[(long)(row + 8) * ldc + col] = make_float2(v2, v3);
            }
        }
    }
}

// ---------------------------------------------------------------------------
// V transpose (fp16): V rows inside qkv [B*S x 3*DIM] -> [B][D][S]
// ---------------------------------------------------------------------------
__global__ __launch_bounds__(256)
void transpose_h(const __half* __restrict__ qkv, __half* __restrict__ out)
{
    __shared__ __half t[32][34];
    const __half* ib = qkv + (long)blockIdx.z * SEQ * (3 * DIM) + 2 * DIM;
    __half*       ob = out + (long)blockIdx.z * DIM * SEQ;
    const int d0 = blockIdx.x * 32;
    const int s0 = blockIdx.y * 32;
    const int tx = threadIdx.x;
    const int ty = threadIdx.y;
    #pragma unroll
    for (int j = 0; j < 32; j += 8)
        t[ty + j][tx] = ib[(long)(s0 + ty + j) * (3 * DIM) + d0 + tx];
    __syncthreads();
    #pragma unroll
    for (int j = 0; j < 32; j += 8)
        ob[(long)(d0 + ty + j) * SEQ + s0 + tx] = t[tx][ty + j];
}

// ---------------------------------------------------------------------------
// In-place row softmax (exact fp32) + fp16 copy for the AV GEMM
// ---------------------------------------------------------------------------
__global__ __launch_bounds__(256)
void softmax_kernel(float* __restrict__ data, __half* __restrict__ ph)
{
    constexpr int NC = SEQ;
    constexpr int PT = NC / 256;

    const long roff = (long)blockIdx.x * NC;
    float*  row = data + roff;
    __half* rh  = ph + roff;
    __shared__ float red[8];

    const int tid  = threadIdx.x;
    const int lane = tid & 31;
    const int warp = tid >> 5;

    float v[PT];
    #pragma unroll
    for (int i = 0; i < PT; ++i) v[i] = row[tid + i * 256];

    float lmax = v[0];
    #pragma unroll
    for (int i = 1; i < PT; ++i) lmax = fmaxf(lmax, v[i]);
    #pragma unroll
    for (int o = 16; o > 0; o >>= 1)
        lmax = fmaxf(lmax, __shfl_xor_sync(0xFFFFFFFFu, lmax, o));
    if (lane == 0) red[warp] = lmax;
    __syncthreads();
    float rmax = red[0];
    #pragma unroll
    for (int w = 1; w < 8; ++w) rmax = fmaxf(rmax, red[w]);
    __syncthreads();

    float lsum = 0.0f;
    #pragma unroll
    for (int i = 0; i < PT; ++i) {
        v[i] = __expf(v[i] - rmax);
        lsum += v[i];
    }
    #pragma unroll
    for (int o = 16; o > 0; o >>= 1)
        lsum += __shfl_xor_sync(0xFFFFFFFFu, lsum, o);
    if (lane == 0) red[warp] = lsum;
    __syncthreads();
    float rsum = 0.0f;
    #pragma unroll
    for (int w = 0; w < 8; ++w) rsum += red[w];

    const float inv = 1.0f / rsum;
    #pragma unroll
    for (int i = 0; i < PT; ++i) {
        const int idx = tid + i * 256;
        const float o = v[i] * inv;
        row[idx] = o;
        rh[idx]  = __float2half_rn(o);
    }
}

// ---------------------------------------------------------------------------
// Launch: cvt -> fused QKV proj -> V^T -> scores -> softmax -> AV
// Output layout: [weighted_sum B*S*D | attention_weights B*S*S]
// ---------------------------------------------------------------------------
extern "C" void kernel_launch(void* const* d_in, const int* in_sizes, int n_in,
                              void* d_out, int out_size)
{
    const float* x  = (const float*)d_in[0];
    const float* Wq = (const float*)d_in[1];
    const float* bq = (const float*)d_in[2];
    const float* Wk = (const float*)d_in[3];
    const float* bk = (const float*)d_in[4];
    const float* Wv = (const float*)d_in[5];
    const float* bv = (const float*)d_in[6];

    float* out_ws = (float*)d_out;
    float* out_aw = (float*)d_out + (long)BATCH * SEQ * DIM;

    __half *xh, *w, *qkv, *vt, *p;
    float* b;
    cudaGetSymbolAddress((void**)&xh,  g_x);
    cudaGetSymbolAddress((void**)&w,   g_w);
    cudaGetSymbolAddress((void**)&b,   g_b);
    cudaGetSymbolAddress((void**)&qkv, g_qkv);
    cudaGetSymbolAddress((void**)&vt,  g_vt);
    cudaGetSymbolAddress((void**)&p,   g_p);

    // smem: 3 stages x 2 tiles x 8192 B = 49152 B
    const int smem_sz = 3 * 2 * 128 * 32 * 2;
    cudaFuncSetAttribute(gemm_h<true >, cudaFuncAttributeMaxDynamicSharedMemorySize, smem_sz);
    cudaFuncSetAttribute(gemm_h<false>, cudaFuncAttributeMaxDynamicSharedMemorySize, smem_sz);

    const dim3 blk(256);

    // 0) convert inputs to fp16 (x; Wq|Wk|Wv concat; bias concat)
    {
        const int nx = BATCH * SEQ * DIM / 4;
        const int nw = DIM * DIM / 4;
        cvt_half_kernel<<<(nx + 255) / 256, blk>>>(x, xh, nx);
        cvt3_kernel<<<(3 * nw + 255) / 256, blk>>>(Wq, Wk, Wv, w, nw);
        bias3_kernel<<<(3 * DIM + 255) / 256, blk>>>(bq, bk, bv, b);
    }

    // 1) Fused QKV projection: [8192, 3072] = xh @ W^T + b, fp16 out
    {
        dim3 grid((3 * DIM) / 128, (BATCH * SEQ) / 128, 1);
        gemm_h<true><<<grid, blk, smem_sz>>>(xh, w, b, qkv,
                                             3 * DIM, DIM,
                                             DIM, DIM, 3 * DIM, 1.0f, 0, 0, 0);
    }

    // 2) V^T: [S,D] (stride 3*DIM inside qkv) -> [D,S] fp16
    {
        dim3 tgrid(DIM / 32, SEQ / 32, BATCH);
        transpose_h<<<tgrid, dim3(32, 8)>>>(qkv, vt);
    }

    // 3) scores = (Q @ K^T) / 32, fp32 into attention-weights region
    {
        dim3 grid(SEQ / 128, SEQ / 128, BATCH);
        gemm_h<false><<<grid, blk, smem_sz>>>(qkv, qkv + DIM, nullptr, out_aw,
                                              SEQ, DIM,
                                              3 * DIM, 3 * DIM, SEQ, 0.03125f,
                                              (long)SEQ * 3 * DIM,
                                              (long)SEQ * 3 * DIM,
                                              (long)SEQ * SEQ);
    }

    // 4) softmax: exact fp32 -> out_aw, fp16 -> p
    softmax_kernel<<<BATCH * SEQ, blk>>>(out_aw, p);

    // 5) weighted_sum = P @ Vt^T  (Vt: [D,S] = B[N=D,K=S]), fp32 out
    {
        dim3 grid(DIM / 128, SEQ / 128, BATCH);
        gemm_h<false><<<grid, blk, smem_sz>>>(p, vt, nullptr, out_ws,
                                              DIM, SEQ,
                                              SEQ, SEQ, DIM, 1.0f,
                                              (long)SEQ * SEQ,
                                              (long)DIM * SEQ,
                                              (long)SEQ * DIM);
    }
}

// round 13
// speedup vs baseline: 1.4062x; 1.0019x over previous
#include <cuda_runtime.h>
#include <cuda_fp16.h>
#include <cstdint>

static constexpr int BATCH = 4;
static constexpr int SEQ   = 2048;
static constexpr int DIM   = 1024;

// Scratch (device globals: allocation-guard safe)
__device__ __half g_x  [BATCH * SEQ * DIM];        // fp16 x
__device__ __half g_w  [3 * DIM * DIM];            // concat Wq|Wk|Wv fp16
__device__ float  g_b  [3 * DIM];                  // concat bq|bk|bv fp32
__device__ __half g_qkv[BATCH * SEQ * 3 * DIM];    // fused Q|K|V rows
__device__ __half g_vt [BATCH * DIM * SEQ];        // V^T: [B][D][S]
__device__ __half g_p  [BATCH * SEQ * SEQ];        // fp16 attention weights

// ---------------------------------------------------------------------------
__device__ __forceinline__ void mma_f16(float (&c)[4],
                                        uint32_t a0, uint32_t a1,
                                        uint32_t a2, uint32_t a3,
                                        uint32_t b0, uint32_t b1) {
    asm volatile(
        "mma.sync.aligned.m16n8k16.row.col.f32.f16.f16.f32 "
        "{%0,%1,%2,%3}, {%4,%5,%6,%7}, {%8,%9}, {%0,%1,%2,%3};\n"
        : "+f"(c[0]), "+f"(c[1]), "+f"(c[2]), "+f"(c[3])
        : "r"(a0), "r"(a1), "r"(a2), "r"(a3), "r"(b0), "r"(b1));
}

__device__ __forceinline__ void ldsm4(uint32_t& r0, uint32_t& r1,
                                      uint32_t& r2, uint32_t& r3, uint32_t addr) {
    asm volatile(
        "ldmatrix.sync.aligned.m8n8.x4.shared.b16 {%0,%1,%2,%3}, [%4];"
        : "=r"(r0), "=r"(r1), "=r"(r2), "=r"(r3) : "r"(addr));
}

#define CPA16(dst, src) \
    asm volatile("cp.async.cg.shared.global [%0], [%1], 16;\n" :: "r"(dst), "l"(src))

// ---------------------------------------------------------------------------
// fp32 -> fp16 conversion passes
// ---------------------------------------------------------------------------
__global__ __launch_bounds__(256)
void cvt_half_kernel(const float* __restrict__ in, __half* __restrict__ out, int n4)
{
    int i = blockIdx.x * 256 + threadIdx.x;
    if (i < n4) {
        float4 v = ((const float4*)in)[i];
        __half2 h01 = __floats2half2_rn(v.x, v.y);
        __half2 h23 = __floats2half2_rn(v.z, v.w);
        uint2 pk;
        pk.x = *(uint32_t*)&h01;
        pk.y = *(uint32_t*)&h23;
        ((uint2*)out)[i] = pk;
    }
}

__global__ __launch_bounds__(256)
void cvt3_kernel(const float* __restrict__ w0, const float* __restrict__ w1,
                 const float* __restrict__ w2, __half* __restrict__ out, int nw4)
{
    int i = blockIdx.x * 256 + threadIdx.x;
    if (i < 3 * nw4) {
        const float* src = (i < nw4) ? w0 : (i < 2 * nw4 ? w1 : w2);
        int j = (i < nw4) ? i : (i < 2 * nw4 ? i - nw4 : i - 2 * nw4);
        float4 v = ((const float4*)src)[j];
        __half2 h01 = __floats2half2_rn(v.x, v.y);
        __half2 h23 = __floats2half2_rn(v.z, v.w);
        uint2 pk;
        pk.x = *(uint32_t*)&h01;
        pk.y = *(uint32_t*)&h23;
        ((uint2*)out)[i] = pk;
    }
}

__global__ __launch_bounds__(256)
void bias3_kernel(const float* __restrict__ b0, const float* __restrict__ b1,
                  const float* __restrict__ b2, float* __restrict__ out)
{
    int i = blockIdx.x * 256 + threadIdx.x;
    if (i < DIM)           out[i] = b0[i];
    else if (i < 2 * DIM)  out[i] = b1[i - DIM];
    else if (i < 3 * DIM)  out[i] = b2[i - 2 * DIM];
}

// ---------------------------------------------------------------------------
// FP16 tensor-core GEMM (fp32 accum):  C = alpha * (A @ B^T) + bias
//   A [M x K] lda, B [N x K] ldb, row-major fp16, explicit leading dims.
// 128x128 block tile. Pair-scheme: 2 sub-tiles of BK=32 (16 KB A+B each)
// per ONE __syncthreads; 3-pair ring (96 KB), 1 cp.async commit per pair.
// ldmatrix fragment loads from XOR-swizzled 64B-row tiles, mma.m16n8k16,
// 256 threads (8 warps, 64x32 warp tiles), 2 CTAs/SM.
//   HALF_OUT: store C fp16 (operand reuse); else fp32.
// ---------------------------------------------------------------------------
template <bool HALF_OUT>
__global__ __launch_bounds__(256, 2)
void gemm_h(const __half* __restrict__ A, const __half* __restrict__ B,
            const float* __restrict__ bias, void* __restrict__ C,
            int N, int K, int lda, int ldb, int ldc, float alpha,
            long sA, long sB, long sC)
{
    constexpr int SUB_H  = 128 * 32;           // halves per matrix sub-tile (8 KB)
    constexpr int PAIR_H = 4 * SUB_H;          // A0,B0,A1,B1 (32 KB)

    extern __shared__ __half smh[];
    uint32_t sbase;
    asm("{ .reg .u64 t; cvta.to.shared.u64 t, %1; cvt.u32.u64 %0, t; }"
        : "=r"(sbase) : "l"(smh));

    const __half* Ab = A + (long)blockIdx.z * sA;
    const __half* Bb = B + (long)blockIdx.z * sB;

    const int n0   = blockIdx.x * 128;
    const int m0   = blockIdx.y * 128;
    const int tid  = threadIdx.x;
    const int warp = tid >> 5;
    const int lane = tid & 31;
    const int g    = lane >> 2;
    const int tg   = lane & 3;
    const int wm   = (warp & 1) * 64;
    const int wn   = (warp >> 1) * 32;

    // Per-lane LDSM addressing
    const int lrow = ((lane >> 3) & 1) * 8 + (lane & 7);   // 0..15
    const uint32_t hi = lane >> 4;                          // 0/1

    uint32_t offA[4], swA[4];
    #pragma unroll
    for (int mi = 0; mi < 4; ++mi) {
        int r = wm + mi * 16 + lrow;
        offA[mi] = (uint32_t)r * 64u;
        swA[mi]  = ((uint32_t)r >> 1) & 3u;
    }
    uint32_t offB[2], swB[2];
    #pragma unroll
    for (int nj = 0; nj < 2; ++nj) {
        int r = wn + nj * 16 + lrow;
        offB[nj] = (uint32_t)r * 64u;
        swB[nj]  = ((uint32_t)r >> 1) & 3u;
    }

    float acc[4][4][4];
    #pragma unroll
    for (int i = 0; i < 4; ++i)
        #pragma unroll
        for (int j = 0; j < 4; ++j)
            #pragma unroll
            for (int r = 0; r < 4; ++r) acc[i][j][r] = 0.0f;

    // Pair loader: pair p covers k = [64p, 64p+64); ring slot = p % 3.
    auto load_pair = [&](int p) {
        const int s  = p % 3;
        const int cr = tid >> 1;
        const int cp = (tid & 1) * 2;
        const uint32_t sw = ((uint32_t)cr >> 1) & 3u;
        #pragma unroll
        for (int sub = 0; sub < 2; ++sub) {
            const int k0 = p * 64 + sub * 32;
            const uint32_t abase = sbase + (uint32_t)(s * PAIR_H + sub * 2 * SUB_H) * 2u
                                         + (uint32_t)cr * 64u;
            const uint32_t bbase = abase + (uint32_t)SUB_H * 2u;
            const __half* asrc = Ab + (long)(m0 + cr) * lda + k0 + cp * 8;
            const __half* bsrc = Bb + (long)(n0 + cr) * ldb + k0 + cp * 8;
            CPA16(abase + ((((uint32_t)cp    ) ^ sw) << 4), asrc);
            CPA16(abase + ((((uint32_t)cp + 1) ^ sw) << 4), asrc + 8);
            CPA16(bbase + ((((uint32_t)cp    ) ^ sw) << 4), bsrc);
            CPA16(bbase + ((((uint32_t)cp + 1) ^ sw) << 4), bsrc + 8);
        }
        asm volatile("cp.async.commit_group;\n");
    };

    const int npairs = K / 64;
    load_pair(0);
    load_pair(1);

    for (int p = 0; p < npairs; ++p) {
        if (p + 1 < npairs) asm volatile("cp.async.wait_group 1;\n");
        else                asm volatile("cp.async.wait_group 0;\n");
        __syncthreads();
        // Slots for pair p+2 are (p+2)%3 == (p-1)%3: computed in iteration
        // p-1; the barrier above guarantees all warps finished that compute.
        if (p + 2 < npairs) load_pair(p + 2);

        const uint32_t pbase = sbase + (uint32_t)((p % 3) * PAIR_H) * 2u;

        #pragma unroll
        for (int sub = 0; sub < 2; ++sub) {
            const uint32_t Ab32 = pbase + (uint32_t)(sub * 2 * SUB_H) * 2u;
            const uint32_t Bb32 = Ab32 + (uint32_t)SUB_H * 2u;
            #pragma unroll
            for (int kk = 0; kk < 2; ++kk) {
                const uint32_t c0 = (uint32_t)(kk * 2) + hi;
                uint32_t af[4][4], bf[2][4];
                #pragma unroll
                for (int mi = 0; mi < 4; ++mi)
                    ldsm4(af[mi][0], af[mi][1], af[mi][2], af[mi][3],
                          Ab32 + offA[mi] + ((c0 ^ swA[mi]) << 4));
                #pragma unroll
                for (int nj = 0; nj < 2; ++nj)
                    ldsm4(bf[nj][0], bf[nj][1], bf[nj][2], bf[nj][3],
                          Bb32 + offB[nj] + ((c0 ^ swB[nj]) << 4));
                #pragma unroll
                for (int mi = 0; mi < 4; ++mi)
                    #pragma unroll
                    for (int ni = 0; ni < 4; ++ni) {
                        const int nj = ni >> 1, lo = ni & 1;
                        mma_f16(acc[mi][ni], af[mi][0], af[mi][1], af[mi][2],
                                af[mi][3], bf[nj][lo], bf[nj][2 + lo]);
                    }
            }
        }
    }

    // Epilogue
    #pragma unroll
    for (int mi = 0; mi < 4; ++mi) {
        const int row = m0 + wm + mi * 16 + g;
        #pragma unroll
        for (int ni = 0; ni < 4; ++ni) {
            const int col = n0 + wn + ni * 8 + tg * 2;
            float v0 = acc[mi][ni][0] * alpha, v1 = acc[mi][ni][1] * alpha;
            float v2 = acc[mi][ni][2] * alpha, v3 = acc[mi][ni][3] * alpha;
            if (bias) {
                float2 b = *(const float2*)&bias[col];
                v0 += b.x; v1 += b.y; v2 += b.x; v3 += b.y;
            }
            if (HALF_OUT) {
                __half* Cb = (__half*)C + (long)blockIdx.z * sC;
                __half2 h0 = __floats2half2_rn(v0, v1);
                __half2 h1 = __floats2half2_rn(v2, v3);
                *(__half2*)&Cb[(long)row * ldc + col]       = h0;
                *(__half2*)&Cb[(long)(row + 8) * ldc + col] = h1;
            } else {
                float* Cb = (float*)C + (long)blockIdx.z * sC;
                *(float2*)&Cb[(long)row * ldc + col]       = make_float2(v0, v1);
                *(float2*)&Cb[(long)(row + 8) * ldc + col] = make_float2(v2, v3);
            }
        }
    }
}

// ---------------------------------------------------------------------------
// V transpose (fp16): V rows inside qkv [B*S x 3*DIM] -> [B][D][S]
// ---------------------------------------------------------------------------
__global__ __launch_bounds__(256)
void transpose_h(const __half* __restrict__ qkv, __half* __restrict__ out)
{
    __shared__ __half t[32][34];
    const __half* ib = qkv + (long)blockIdx.z * SEQ * (3 * DIM) + 2 * DIM;
    __half*       ob = out + (long)blockIdx.z * DIM * SEQ;
    const int d0 = blockIdx.x * 32;
    const int s0 = blockIdx.y * 32;
    const int tx = threadIdx.x;
    const int ty = threadIdx.y;
    #pragma unroll
    for (int j = 0; j < 32; j += 8)
        t[ty + j][tx] = ib[(long)(s0 + ty + j) * (3 * DIM) + d0 + tx];
    __syncthreads();
    #pragma unroll
    for (int j = 0; j < 32; j += 8)
        ob[(long)(d0 + ty + j) * SEQ + s0 + tx] = t[tx][ty + j];
}

// ---------------------------------------------------------------------------
// Row softmax, float4-vectorized: thread t owns elements [8t, 8t+8).
// Exact fp32 -> data (in place); fp16 copy -> ph.
// ---------------------------------------------------------------------------
__global__ __launch_bounds__(256)
void softmax_kernel(float* __restrict__ data, __half* __restrict__ ph)
{
    const long roff = (long)blockIdx.x * SEQ;
    float4* r4 = (float4*)(data + roff);
    uint4*  h4 = (uint4*)(ph + roff);
    __shared__ float red[8];

    const int tid  = threadIdx.x;
    const int lane = tid & 31;
    const int warp = tid >> 5;

    float4 va = r4[2 * tid];
    float4 vb = r4[2 * tid + 1];

    float lmax = fmaxf(fmaxf(fmaxf(va.x, va.y), fmaxf(va.z, va.w)),
                       fmaxf(fmaxf(vb.x, vb.y), fmaxf(vb.z, vb.w)));
    #pragma unroll
    for (int o = 16; o > 0; o >>= 1)
        lmax = fmaxf(lmax, __shfl_xor_sync(0xFFFFFFFFu, lmax, o));
    if (lane == 0) red[warp] = lmax;
    __syncthreads();
    float rmax = red[0];
    #pragma unroll
    for (int w = 1; w < 8; ++w) rmax = fmaxf(rmax, red[w]);
    __syncthreads();

    va.x = __expf(va.x - rmax); va.y = __expf(va.y - rmax);
    va.z = __expf(va.z - rmax); va.w = __expf(va.w - rmax);
    vb.x = __expf(vb.x - rmax); vb.y = __expf(vb.y - rmax);
    vb.z = __expf(vb.z - rmax); vb.w = __expf(vb.w - rmax);

    float lsum = (va.x + va.y) + (va.z + va.w) + (vb.x + vb.y) + (vb.z + vb.w);
    #pragma unroll
    for (int o = 16; o > 0; o >>= 1)
        lsum += __shfl_xor_sync(0xFFFFFFFFu, lsum, o);
    if (lane == 0) red[warp] = lsum;
    __syncthreads();
    float rsum = 0.0f;
    #pragma unroll
    for (int w = 0; w < 8; ++w) rsum += red[w];

    const float inv = 1.0f / rsum;
    va.x *= inv; va.y *= inv; va.z *= inv; va.w *= inv;
    vb.x *= inv; vb.y *= inv; vb.z *= inv; vb.w *= inv;

    r4[2 * tid]     = va;
    r4[2 * tid + 1] = vb;

    __half2 p0 = __floats2half2_rn(va.x, va.y);
    __half2 p1 = __floats2half2_rn(va.z, va.w);
    __half2 p2 = __floats2half2_rn(vb.x, vb.y);
    __half2 p3 = __floats2half2_rn(vb.z, vb.w);
    uint4 pk;
    pk.x = *(uint32_t*)&p0; pk.y = *(uint32_t*)&p1;
    pk.z = *(uint32_t*)&p2; pk.w = *(uint32_t*)&p3;
    h4[tid] = pk;
}

// ---------------------------------------------------------------------------
// Launch: cvt -> fused QKV proj -> V^T -> scores -> softmax -> AV
// Output layout: [weighted_sum B*S*D | attention_weights B*S*S]
// ---------------------------------------------------------------------------
extern "C" void kernel_launch(void* const* d_in, const int* in_sizes, int n_in,
                              void* d_out, int out_size)
{
    const float* x  = (const float*)d_in[0];
    const float* Wq = (const float*)d_in[1];
    const float* bq = (const float*)d_in[2];
    const float* Wk = (const float*)d_in[3];
    const float* bk = (const float*)d_in[4];
    const float* Wv = (const float*)d_in[5];
    const float* bv = (const float*)d_in[6];

    float* out_ws = (float*)d_out;
    float* out_aw = (float*)d_out + (long)BATCH * SEQ * DIM;

    __half *xh, *w, *qkv, *vt, *p;
    float* b;
    cudaGetSymbolAddress((void**)&xh,  g_x);
    cudaGetSymbolAddress((void**)&w,   g_w);
    cudaGetSymbolAddress((void**)&b,   g_b);
    cudaGetSymbolAddress((void**)&qkv, g_qkv);
    cudaGetSymbolAddress((void**)&vt,  g_vt);
    cudaGetSymbolAddress((void**)&p,   g_p);

    // smem: 3 pairs x 32768 B = 98304 B per CTA (2 CTAs/SM = 192 KB)
    const int smem_sz = 3 * 4 * 128 * 32 * 2;
    cudaFuncSetAttribute(gemm_h<true >, cudaFuncAttributeMaxDynamicSharedMemorySize, smem_sz);
    cudaFuncSetAttribute(gemm_h<false>, cudaFuncAttributeMaxDynamicSharedMemorySize, smem_sz);

    const dim3 blk(256);

    // 0) convert inputs to fp16 (x; Wq|Wk|Wv concat; bias concat)
    {
        const int nx = BATCH * SEQ * DIM / 4;
        const int nw = DIM * DIM / 4;
        cvt_half_kernel<<<(nx + 255) / 256, blk>>>(x, xh, nx);
        cvt3_kernel<<<(3 * nw + 255) / 256, blk>>>(Wq, Wk, Wv, w, nw);
        bias3_kernel<<<(3 * DIM + 255) / 256, blk>>>(bq, bk, bv, b);
    }

    // 1) Fused QKV projection: [8192, 3072] = xh @ W^T + b, fp16 out
    {
        dim3 grid((3 * DIM) / 128, (BATCH * SEQ) / 128, 1);
        gemm_h<true><<<grid, blk, smem_sz>>>(xh, w, b, qkv,
                                             3 * DIM, DIM,
                                             DIM, DIM, 3 * DIM, 1.0f, 0, 0, 0);
    }

    // 2) V^T: [S,D] (stride 3*DIM inside qkv) -> [D,S] fp16
    {
        dim3 tgrid(DIM / 32, SEQ / 32, BATCH);
        transpose_h<<<tgrid, dim3(32, 8)>>>(qkv, vt);
    }

    // 3) scores = (Q @ K^T) / 32, fp32 into attention-weights region
    {
        dim3 grid(SEQ / 128, SEQ / 128, BATCH);
        gemm_h<false><<<grid, blk, smem_sz>>>(qkv, qkv + DIM, nullptr, out_aw,
                                              SEQ, DIM,
                                              3 * DIM, 3 * DIM, SEQ, 0.03125f,
                                              (long)SEQ * 3 * DIM,
                                              (long)SEQ * 3 * DIM,
                                              (long)SEQ * SEQ);
    }

    // 4) softmax: exact fp32 -> out_aw, fp16 -> p
    softmax_kernel<<<BATCH * SEQ, blk>>>(out_aw, p);

    // 5) weighted_sum = P @ Vt^T  (Vt: [D,S] = B[N=D,K=S]), fp32 out
    {
        dim3 grid(DIM / 128, SEQ / 128, BATCH);
        gemm_h<false><<<grid, blk, smem_sz>>>(p, vt, nullptr, out_ws,
                                              DIM, SEQ,
                                              SEQ, SEQ, DIM, 1.0f,
                                              (long)SEQ * SEQ,
                                              (long)DIM * SEQ,
                                              (long)SEQ * DIM);
    }
}